// round 1
// baseline (speedup 1.0000x reference)
#include <cuda_runtime.h>
#include <cuda_bf16.h>
#include <math.h>

// ---------------- problem constants ----------------
#define BATCH   2
#define SEQLEN  512
#define DMODEL  1024
#define DIN     4384          // D_IN_PROJ
#define DINNER  2048
#define CONVD   2304          // CONV_DIM
#define DSTATE  128
#define NHEADS  32
#define HEADD   64
#define NCLS    48
#define NTOK    (BATCH*SEQLEN)   // 1024

// ---------------- device scratch ----------------
__device__ float g_zx   [(size_t)NTOK * DIN];      // in_proj output (18MB)
__device__ float g_xbc  [(size_t)NTOK * CONVD];    // conv+silu output (9.4MB)
__device__ float g_dts  [(size_t)NTOK * NHEADS];
__device__ float g_dAs  [(size_t)NTOK * NHEADS];
__device__ float g_y0   [(size_t)NTOK * DINNER];   // scan partial (n half 0)
__device__ float g_y1   [(size_t)NTOK * DINNER];   // scan partial (n half 1)
__device__ float g_hn   [(size_t)NTOK * DINNER];   // normed hidden

// ================= Kernel 1: in_proj GEMM =================
// C[M=1024, N=4384] = A[1024,1024] @ W[1024,4384], fp32, 128x128x16 tiles
__global__ void __launch_bounds__(256) k_gemm_in(const float* __restrict__ A,
                                                 const float* __restrict__ W)
{
    const int K = DMODEL, N = DIN;
    __shared__ float As[16][128];
    __shared__ float Bs[16][128];

    int tid = threadIdx.x;
    int tx  = tid & 15, ty = tid >> 4;
    int row0 = blockIdx.y * 128;
    int col0 = blockIdx.x * 128;

    int aRow = tid >> 2;           // 0..63
    int aCol = (tid & 3) * 4;      // 0,4,8,12
    int bRow = tid >> 4;           // 0..15
    int bCol = (tid & 15) * 4;     // 0..60

    float4 pa0, pa1, pb0, pb1;
    const float4 z4 = make_float4(0.f, 0.f, 0.f, 0.f);

    // prefetch tile 0
    pa0 = *(const float4*)&A[(size_t)(row0 + aRow) * K + aCol];
    pa1 = *(const float4*)&A[(size_t)(row0 + aRow + 64) * K + aCol];
    {
        int c0 = col0 + bCol, c1 = col0 + bCol + 64;
        pb0 = (c0 < N) ? *(const float4*)&W[(size_t)bRow * N + c0] : z4;
        pb1 = (c1 < N) ? *(const float4*)&W[(size_t)bRow * N + c1] : z4;
    }

    float acc[8][8];
#pragma unroll
    for (int i = 0; i < 8; ++i)
#pragma unroll
        for (int j = 0; j < 8; ++j) acc[i][j] = 0.f;

    for (int kt = 0; kt < K / 16; ++kt) {
        As[aCol+0][aRow]    = pa0.x; As[aCol+1][aRow]    = pa0.y;
        As[aCol+2][aRow]    = pa0.z; As[aCol+3][aRow]    = pa0.w;
        As[aCol+0][aRow+64] = pa1.x; As[aCol+1][aRow+64] = pa1.y;
        As[aCol+2][aRow+64] = pa1.z; As[aCol+3][aRow+64] = pa1.w;
        *(float4*)&Bs[bRow][bCol]      = pb0;
        *(float4*)&Bs[bRow][bCol + 64] = pb1;
        __syncthreads();

        if (kt + 1 < K / 16) {
            int k0 = (kt + 1) * 16;
            pa0 = *(const float4*)&A[(size_t)(row0 + aRow) * K + k0 + aCol];
            pa1 = *(const float4*)&A[(size_t)(row0 + aRow + 64) * K + k0 + aCol];
            int c0 = col0 + bCol, c1 = col0 + bCol + 64;
            pb0 = (c0 < N) ? *(const float4*)&W[(size_t)(k0 + bRow) * N + c0] : z4;
            pb1 = (c1 < N) ? *(const float4*)&W[(size_t)(k0 + bRow) * N + c1] : z4;
        }

#pragma unroll
        for (int kk = 0; kk < 16; ++kk) {
            float a[8], b[8];
            *(float4*)&a[0] = *(const float4*)&As[kk][ty * 8];
            *(float4*)&a[4] = *(const float4*)&As[kk][ty * 8 + 4];
            *(float4*)&b[0] = *(const float4*)&Bs[kk][tx * 8];
            *(float4*)&b[4] = *(const float4*)&Bs[kk][tx * 8 + 4];
#pragma unroll
            for (int i = 0; i < 8; ++i)
#pragma unroll
                for (int j = 0; j < 8; ++j)
                    acc[i][j] = fmaf(a[i], b[j], acc[i][j]);
        }
        __syncthreads();
    }

#pragma unroll
    for (int i = 0; i < 8; ++i) {
        int row = row0 + ty * 8 + i;
        float* cp = &g_zx[(size_t)row * N + col0 + tx * 8];
        if (col0 + tx * 8 < N)
            *(float4*)cp = make_float4(acc[i][0], acc[i][1], acc[i][2], acc[i][3]);
        if (col0 + tx * 8 + 4 < N)
            *(float4*)(cp + 4) = make_float4(acc[i][4], acc[i][5], acc[i][6], acc[i][7]);
    }
}

// ================= Kernel 2: depthwise conv + SiLU + dt/dA =================
__global__ void __launch_bounds__(256) k_conv(const float* __restrict__ cw,
                                              const float* __restrict__ cb,
                                              const float* __restrict__ dtb,
                                              const float* __restrict__ Alog)
{
    const int PER = CONVD + NHEADS;  // 2336
    int idx = blockIdx.x * 256 + threadIdx.x;
    if (idx >= NTOK * PER) return;
    int c      = idx % PER;
    int tokidx = idx / PER;          // b*512 + l
    int l      = tokidx & (SEQLEN - 1);

    if (c < CONVD) {
        float acc = cb[c];
#pragma unroll
        for (int j = 0; j < 4; ++j) {
            int lj = l - 3 + j;
            if (lj >= 0)
                acc = fmaf(cw[c * 4 + j],
                           g_zx[(size_t)(tokidx - 3 + j) * DIN + DINNER + c], acc);
        }
        acc = acc / (1.f + expf(-acc));                    // silu
        g_xbc[(size_t)tokidx * CONVD + c] = acc;
    } else {
        int h = c - CONVD;
        float raw = g_zx[(size_t)tokidx * DIN + (DINNER + CONVD) + h] + dtb[h];
        float sp  = (raw > 15.f) ? raw : log1pf(expf(raw));  // softplus
        g_dts[(size_t)tokidx * NHEADS + h] = sp;
        g_dAs[(size_t)tokidx * NHEADS + h] = expf(sp * (-expf(Alog[h])));
    }
}

// ================= Kernel 3: selective scan =================
// 128 blocks = (b, h, n-half). Each block: state[64 p][64 n] in registers.
__global__ void __launch_bounds__(256) k_scan()
{
    int blk  = blockIdx.x;
    int b    = blk >> 6;
    int rem  = blk & 63;
    int h    = rem >> 1;
    int half = rem & 1;
    int tid  = threadIdx.x;
    int p = tid >> 2, q = tid & 3;

    __shared__ float xs[64], Bsh[64], Csh[64];
    __shared__ float sdt[SEQLEN], sdA[SEQLEN];

    // stage all dt / dA for this (b,h) once
    for (int t = tid; t < SEQLEN; t += 256) {
        sdt[t] = g_dts[(size_t)(b * SEQLEN + t) * NHEADS + h];
        sdA[t] = g_dAs[(size_t)(b * SEQLEN + t) * NHEADS + h];
    }

    float s[16];
#pragma unroll
    for (int j = 0; j < 16; ++j) s[j] = 0.f;

    float* yout = half ? g_y1 : g_y0;
    const float* base = g_xbc + (size_t)(b * SEQLEN) * CONVD;

    int role   = tid >> 6;   // 0:x  1:B  2:C  3:idle
    int lane64 = tid & 63;
    int off = (role == 0) ? (h * HEADD + lane64)
            : (role == 1) ? (DINNER + half * 64 + lane64)
                          : (DINNER + DSTATE + half * 64 + lane64);
    float pre = 0.f;
    if (role < 3) pre = base[off];
    __syncthreads();

    for (int t = 0; t < SEQLEN; ++t) {
        if (role == 0)      xs[lane64]  = pre;
        else if (role == 1) Bsh[lane64] = pre;
        else if (role == 2) Csh[lane64] = pre;
        __syncthreads();
        if (t + 1 < SEQLEN && role < 3)
            pre = base[(size_t)(t + 1) * CONVD + off];   // prefetch next step

        float dtv = sdt[t], dAv = sdA[t];
        float xd = xs[p] * dtv;
        float y = 0.f;
#pragma unroll
        for (int j = 0; j < 16; ++j) {
            int n = q * 16 + j;
            s[j] = fmaf(s[j], dAv, xd * Bsh[n]);
            y    = fmaf(s[j], Csh[n], y);
        }
        y += __shfl_xor_sync(0xffffffffu, y, 1);
        y += __shfl_xor_sync(0xffffffffu, y, 2);
        if (q == 0)
            yout[((size_t)(b * SEQLEN + t) * NHEADS + h) * HEADD + p] = y;
        __syncthreads();
    }
}

// ================= Kernel 4: gating + RMSNorm =================
__global__ void __launch_bounds__(256) k_gatenorm(const float* __restrict__ Dv,
                                                  const float* __restrict__ nw)
{
    int tok = blockIdx.x;
    int tid = threadIdx.x;
    __shared__ float gsh[DINNER];
    __shared__ float red[8];
    __shared__ float scale_s;

    float ss = 0.f;
#pragma unroll
    for (int k = 0; k < 8; ++k) {
        int i = tid + k * 256;
        int h = i >> 6;
        float x  = g_xbc[(size_t)tok * CONVD + i];
        float yv = g_y0[(size_t)tok * DINNER + i] + g_y1[(size_t)tok * DINNER + i]
                 + Dv[h] * x;
        float z  = g_zx[(size_t)tok * DIN + i];
        float g  = yv * (z / (1.f + expf(-z)));
        gsh[i] = g;
        ss = fmaf(g, g, ss);
    }
#pragma unroll
    for (int o = 16; o; o >>= 1) ss += __shfl_xor_sync(0xffffffffu, ss, o);
    if ((tid & 31) == 0) red[tid >> 5] = ss;
    __syncthreads();
    if (tid == 0) {
        float tot = 0.f;
#pragma unroll
        for (int w = 0; w < 8; ++w) tot += red[w];
        scale_s = rsqrtf(tot / (float)DINNER + 1e-5f);
    }
    __syncthreads();
    float sc = scale_s;
#pragma unroll
    for (int k = 0; k < 8; ++k) {
        int i = tid + k * 256;
        g_hn[(size_t)tok * DINNER + i] = gsh[i] * sc * nw[i];
    }
}

// ================= Kernel 5: classifier GEMM =================
// out[1024,48] = hn[1024,2048] @ Wc[2048,48] + b. 16 tokens / block.
__global__ void __launch_bounds__(256) k_cls(const float* __restrict__ Wc,
                                             const float* __restrict__ bc,
                                             float* __restrict__ out)
{
    int tok0 = blockIdx.x * 16;
    int tid  = threadIdx.x;
    __shared__ float Ws[64 * 48];   // 12KB
    __shared__ float Hs[16 * 64];   // 4KB
    int tokl = tid >> 4;            // 0..15
    int c0   = (tid & 15) * 3;      // 0..45
    float a0 = 0.f, a1 = 0.f, a2 = 0.f;

    for (int k0 = 0; k0 < DINNER; k0 += 64) {
#pragma unroll
        for (int r = 0; r < 12; ++r) {
            int idx = tid + r * 256;
            Ws[idx] = Wc[(size_t)k0 * NCLS + idx];
        }
#pragma unroll
        for (int r = 0; r < 4; ++r) {
            int idx = tid + r * 256;
            Hs[idx] = g_hn[(size_t)(tok0 + (idx >> 6)) * DINNER + k0 + (idx & 63)];
        }
        __syncthreads();
#pragma unroll
        for (int kk = 0; kk < 64; ++kk) {
            float hv = Hs[tokl * 64 + kk];
            const float* wr = &Ws[kk * 48 + c0];
            a0 = fmaf(hv, wr[0], a0);
            a1 = fmaf(hv, wr[1], a1);
            a2 = fmaf(hv, wr[2], a2);
        }
        __syncthreads();
    }
    float* op = &out[(size_t)(tok0 + tokl) * NCLS + c0];
    op[0] = a0 + bc[c0];
    op[1] = a1 + bc[c0 + 1];
    op[2] = a2 + bc[c0 + 2];
}

// ================= launcher =================
extern "C" void kernel_launch(void* const* d_in, const int* in_sizes, int n_in,
                              void* d_out, int out_size)
{
    const float* inputs  = (const float*)d_in[0];
    const float* W_in    = (const float*)d_in[1];
    const float* conv_w  = (const float*)d_in[2];
    const float* conv_b  = (const float*)d_in[3];
    const float* dt_bias = (const float*)d_in[4];
    const float* A_log   = (const float*)d_in[5];
    const float* Dv      = (const float*)d_in[6];
    const float* norm_w  = (const float*)d_in[7];
    /* d_in[8] = W_out (unused by reference output path) */
    const float* W_cls   = (const float*)d_in[9];
    const float* b_cls   = (const float*)d_in[10];
    float* out = (float*)d_out;

    (void)in_sizes; (void)n_in; (void)out_size;

    // 1) in_proj GEMM
    {
        dim3 grid((DIN + 127) / 128, NTOK / 128);
        k_gemm_in<<<grid, 256>>>(inputs, W_in);
    }
    // 2) conv + activations + dt/dA
    {
        int tot = NTOK * (CONVD + NHEADS);
        k_conv<<<(tot + 255) / 256, 256>>>(conv_w, conv_b, dt_bias, A_log);
    }
    // 3) scan
    k_scan<<<128, 256>>>();
    // 4) gate + rmsnorm
    k_gatenorm<<<NTOK, 256>>>(Dv, norm_w);
    // 5) classifier
    k_cls<<<NTOK / 16, 256>>>(W_cls, b_cls, out);
}

// round 3
// speedup vs baseline: 1.2275x; 1.2275x over previous
#include <cuda_runtime.h>
#include <cuda_bf16.h>
#include <math.h>
#include <cstdint>

// ---------------- problem constants ----------------
#define BATCH   2
#define SEQLEN  512
#define DMODEL  1024
#define DIN     4384          // D_IN_PROJ
#define DINNER  2048
#define CONVD   2304          // CONV_DIM
#define DSTATE  128
#define NHEADS  32
#define HEADD   64
#define NCLS    48
#define NTOK    (BATCH*SEQLEN)   // 1024

// split-K stacked GEMM constants
#define KSTACK  3072          // 3 * DMODEL
#define NPAD    4480          // DIN padded to multiple of 128
#define KTILE   32
#define NKT     (KSTACK/KTILE)   // 96
#define SMSTRIDE 40           // bf16 per smem row (80B) - conflict-free ldmatrix

// ---------------- device scratch ----------------
__device__ float g_zx   [(size_t)NTOK * DIN];      // in_proj output (18MB)
__device__ float g_xbc  [(size_t)NTOK * CONVD];    // conv+silu output (9.4MB)
__device__ float g_dts  [(size_t)NTOK * NHEADS];
__device__ float g_dAs  [(size_t)NTOK * NHEADS];
__device__ float g_y0   [(size_t)NTOK * DINNER];   // scan partial (n half 0)
__device__ float g_y1   [(size_t)NTOK * DINNER];   // scan partial (n half 1)
__device__ float g_hn   [(size_t)NTOK * DINNER];   // normed hidden
__device__ __nv_bfloat16 g_Astk[(size_t)NTOK * KSTACK];   // [Ahi|Ahi|Alo]  6MB
__device__ __nv_bfloat16 g_Bstk[(size_t)NPAD * KSTACK];   // [Bhi|Blo|Bhi] 27.5MB

// ================= warp-MMA helpers =================
__device__ __forceinline__ uint32_t smem_u32(const void* p) {
    uint32_t a;
    asm("{ .reg .u64 t; cvta.to.shared.u64 t, %1; cvt.u32.u64 %0, t; }"
        : "=r"(a) : "l"(p));
    return a;
}
__device__ __forceinline__ void ldsm4(uint32_t& r0, uint32_t& r1,
                                      uint32_t& r2, uint32_t& r3, uint32_t addr) {
    asm volatile("ldmatrix.sync.aligned.m8n8.x4.shared.b16 {%0,%1,%2,%3}, [%4];"
                 : "=r"(r0), "=r"(r1), "=r"(r2), "=r"(r3) : "r"(addr));
}
__device__ __forceinline__ void mma16816(float* c, const uint32_t* a,
                                         uint32_t b0, uint32_t b1) {
    asm volatile(
        "mma.sync.aligned.m16n8k16.row.col.f32.bf16.bf16.f32 "
        "{%0,%1,%2,%3}, {%4,%5,%6,%7}, {%8,%9}, {%0,%1,%2,%3};"
        : "+f"(c[0]), "+f"(c[1]), "+f"(c[2]), "+f"(c[3])
        : "r"(a[0]), "r"(a[1]), "r"(a[2]), "r"(a[3]), "r"(b0), "r"(b1));
}

// ================= Kernel 1a: split A into bf16 stack =================
__global__ void __launch_bounds__(256) k_cvtA(const float* __restrict__ A)
{
    int idx = blockIdx.x * 256 + threadIdx.x;      // M*K = 1M
    int m = idx >> 10, k = idx & 1023;
    float v = A[idx];
    __nv_bfloat16 hi = __float2bfloat16(v);
    __nv_bfloat16 lo = __float2bfloat16(v - __bfloat162float(hi));
    __nv_bfloat16* row = g_Astk + (size_t)m * KSTACK;
    row[k]        = hi;
    row[1024 + k] = hi;
    row[2048 + k] = lo;
}

// ================= Kernel 1b: transpose + split W into bf16 stack =====
// Bstk[n][k] segments: [hi(W[k][n]) | lo | hi], n padded to 4480 (zeros).
__global__ void __launch_bounds__(256) k_cvtW(const float* __restrict__ W)
{
    __shared__ float tile[32][33];
    int k0 = blockIdx.x * 32;
    int n0 = blockIdx.y * 32;
    int t  = threadIdx.x;
    int tn = t & 31, tk8 = t >> 5;                 // 0..31, 0..7
#pragma unroll
    for (int i = 0; i < 4; ++i) {
        int kr = tk8 * 4 + i;
        int n  = n0 + tn;
        tile[kr][tn] = (n < DIN) ? W[(size_t)(k0 + kr) * DIN + n] : 0.f;
    }
    __syncthreads();
#pragma unroll
    for (int i = 0; i < 4; ++i) {
        int nr = tk8 * 4 + i;
        float v = tile[tn][nr];                    // = W[k0+tn][n0+nr]
        __nv_bfloat16 hi = __float2bfloat16(v);
        __nv_bfloat16 lo = __float2bfloat16(v - __bfloat162float(hi));
        __nv_bfloat16* row = g_Bstk + (size_t)(n0 + nr) * KSTACK + k0 + tn;
        row[0]    = hi;
        row[1024] = lo;
        row[2048] = hi;
    }
}

// ================= Kernel 1c: bf16 HMMA split GEMM =================
// g_zx[M=1024, N=4384] = Astk[1024,3072] @ Bstk[4480,3072]^T
// CTA 128x128, warp tile 32x64 (4x2 warp grid), K-tile 32, double buffer.
__global__ void __launch_bounds__(256) k_gemm_mma()
{
    __shared__ __nv_bfloat16 As[2][128 * SMSTRIDE];
    __shared__ __nv_bfloat16 Bs[2][128 * SMSTRIDE];

    const int tid = threadIdx.x;
    const int wid = tid >> 5, lid = tid & 31;
    const int row0 = blockIdx.y * 128;
    const int col0 = blockIdx.x * 128;
    const int wm = wid >> 1;     // 0..3 : rows wm*32
    const int wn = wid & 1;      // 0..1 : cols wn*64

    // global->smem mapping: unit u in [0,512): row=u>>2, seg=u&3 (16B)
    const int grow = tid >> 2;       // 0..63
    const int gseg = tid & 3;        // 0..3

    const __nv_bfloat16* Ag = g_Astk + (size_t)(row0 + grow) * KSTACK + gseg * 8;
    const __nv_bfloat16* Bg = g_Bstk + (size_t)(col0 + grow) * KSTACK + gseg * 8;
    const size_t half64 = (size_t)64 * KSTACK;

    uint4 pa0, pa1, pb0, pb1;
    pa0 = *(const uint4*)(Ag);
    pa1 = *(const uint4*)(Ag + half64);
    pb0 = *(const uint4*)(Bg);
    pb1 = *(const uint4*)(Bg + half64);

    float acc[2][8][4];
#pragma unroll
    for (int i = 0; i < 2; ++i)
#pragma unroll
        for (int j = 0; j < 8; ++j)
#pragma unroll
            for (int v = 0; v < 4; ++v) acc[i][j][v] = 0.f;

    // ldmatrix per-lane row/k offsets
    const int lrow = lid & 15;            // row within 16-row group
    const int lk   = (lid >> 4) * 16;     // byte offset for k-half (8 bf16)

    const uint32_t smA[2] = { smem_u32(As[0]), smem_u32(As[1]) };
    const uint32_t smB[2] = { smem_u32(Bs[0]), smem_u32(Bs[1]) };

    for (int c = 0; c < NKT; ++c) {
        int buf = c & 1;
        // store prefetched tile
        {
            char* a = (char*)As[buf];
            char* b = (char*)Bs[buf];
            int off = grow * (SMSTRIDE * 2) + gseg * 16;
            *(uint4*)(a + off) = pa0;
            *(uint4*)(a + off + 64 * (SMSTRIDE * 2)) = pa1;
            *(uint4*)(b + off) = pb0;
            *(uint4*)(b + off + 64 * (SMSTRIDE * 2)) = pb1;
        }
        __syncthreads();

        if (c + 1 < NKT) {
            int k0 = (c + 1) * KTILE;
            pa0 = *(const uint4*)(Ag + k0);
            pa1 = *(const uint4*)(Ag + k0 + half64);
            pb0 = *(const uint4*)(Bg + k0);
            pb1 = *(const uint4*)(Bg + k0 + half64);
        }

        uint32_t Ab = smA[buf], Bb = smB[buf];
#pragma unroll
        for (int s = 0; s < 2; ++s) {
            uint32_t a[2][4];
#pragma unroll
            for (int mi = 0; mi < 2; ++mi) {
                uint32_t addr = Ab + (wm * 32 + mi * 16 + lrow) * (SMSTRIDE * 2)
                              + s * 32 + lk;
                ldsm4(a[mi][0], a[mi][1], a[mi][2], a[mi][3], addr);
            }
            uint32_t b[4][4];
#pragma unroll
            for (int nj = 0; nj < 4; ++nj) {
                uint32_t addr = Bb + (wn * 64 + nj * 16 + lrow) * (SMSTRIDE * 2)
                              + s * 32 + lk;
                ldsm4(b[nj][0], b[nj][1], b[nj][2], b[nj][3], addr);
            }
#pragma unroll
            for (int mi = 0; mi < 2; ++mi)
#pragma unroll
                for (int nj = 0; nj < 8; ++nj) {
                    int q = nj >> 1, r = nj & 1;
                    mma16816(acc[mi][nj], a[mi], b[q][r], b[q][r + 2]);
                }
        }
        __syncthreads();
    }

    // epilogue: direct stores (quad-contiguous 32B sectors)
    const int crow = lid >> 2;
    const int ccol = (lid & 3) * 2;
#pragma unroll
    for (int mi = 0; mi < 2; ++mi) {
#pragma unroll
        for (int nj = 0; nj < 8; ++nj) {
            int col = col0 + wn * 64 + nj * 8 + ccol;
            if (col < DIN) {
                int r = row0 + wm * 32 + mi * 16 + crow;
                *(float2*)&g_zx[(size_t)r * DIN + col] =
                    make_float2(acc[mi][nj][0], acc[mi][nj][1]);
                *(float2*)&g_zx[(size_t)(r + 8) * DIN + col] =
                    make_float2(acc[mi][nj][2], acc[mi][nj][3]);
            }
        }
    }
}

// ================= Kernel 2: depthwise conv + SiLU + dt/dA =================
__global__ void __launch_bounds__(256) k_conv(const float* __restrict__ cw,
                                              const float* __restrict__ cb,
                                              const float* __restrict__ dtb,
                                              const float* __restrict__ Alog)
{
    const int PER = CONVD + NHEADS;  // 2336
    int idx = blockIdx.x * 256 + threadIdx.x;
    if (idx >= NTOK * PER) return;
    int c      = idx % PER;
    int tokidx = idx / PER;          // b*512 + l
    int l      = tokidx & (SEQLEN - 1);

    if (c < CONVD) {
        float acc = cb[c];
#pragma unroll
        for (int j = 0; j < 4; ++j) {
            int lj = l - 3 + j;
            if (lj >= 0)
                acc = fmaf(cw[c * 4 + j],
                           g_zx[(size_t)(tokidx - 3 + j) * DIN + DINNER + c], acc);
        }
        acc = acc / (1.f + expf(-acc));                    // silu
        g_xbc[(size_t)tokidx * CONVD + c] = acc;
    } else {
        int h = c - CONVD;
        float raw = g_zx[(size_t)tokidx * DIN + (DINNER + CONVD) + h] + dtb[h];
        float sp  = (raw > 15.f) ? raw : log1pf(expf(raw));  // softplus
        g_dts[(size_t)tokidx * NHEADS + h] = sp;
        g_dAs[(size_t)tokidx * NHEADS + h] = expf(sp * (-expf(Alog[h])));
    }
}

// ================= Kernel 3: selective scan =================
__global__ void __launch_bounds__(256) k_scan()
{
    int blk  = blockIdx.x;
    int b    = blk >> 6;
    int rem  = blk & 63;
    int h    = rem >> 1;
    int half = rem & 1;
    int tid  = threadIdx.x;
    int p = tid >> 2, q = tid & 3;

    __shared__ float xs[64], Bsh[64], Csh[64];
    __shared__ float sdt[SEQLEN], sdA[SEQLEN];

    for (int t = tid; t < SEQLEN; t += 256) {
        sdt[t] = g_dts[(size_t)(b * SEQLEN + t) * NHEADS + h];
        sdA[t] = g_dAs[(size_t)(b * SEQLEN + t) * NHEADS + h];
    }

    float s[16];
#pragma unroll
    for (int j = 0; j < 16; ++j) s[j] = 0.f;

    float* yout = half ? g_y1 : g_y0;
    const float* base = g_xbc + (size_t)(b * SEQLEN) * CONVD;

    int role   = tid >> 6;
    int lane64 = tid & 63;
    int off = (role == 0) ? (h * HEADD + lane64)
            : (role == 1) ? (DINNER + half * 64 + lane64)
                          : (DINNER + DSTATE + half * 64 + lane64);
    float pre = 0.f;
    if (role < 3) pre = base[off];
    __syncthreads();

    for (int t = 0; t < SEQLEN; ++t) {
        if (role == 0)      xs[lane64]  = pre;
        else if (role == 1) Bsh[lane64] = pre;
        else if (role == 2) Csh[lane64] = pre;
        __syncthreads();
        if (t + 1 < SEQLEN && role < 3)
            pre = base[(size_t)(t + 1) * CONVD + off];

        float dtv = sdt[t], dAv = sdA[t];
        float xd = xs[p] * dtv;
        float y = 0.f;
#pragma unroll
        for (int j = 0; j < 16; ++j) {
            int n = q * 16 + j;
            s[j] = fmaf(s[j], dAv, xd * Bsh[n]);
            y    = fmaf(s[j], Csh[n], y);
        }
        y += __shfl_xor_sync(0xffffffffu, y, 1);
        y += __shfl_xor_sync(0xffffffffu, y, 2);
        if (q == 0)
            yout[((size_t)(b * SEQLEN + t) * NHEADS + h) * HEADD + p] = y;
        __syncthreads();
    }
}

// ================= Kernel 4: gating + RMSNorm =================
__global__ void __launch_bounds__(256) k_gatenorm(const float* __restrict__ Dv,
                                                  const float* __restrict__ nw)
{
    int tok = blockIdx.x;
    int tid = threadIdx.x;
    __shared__ float gsh[DINNER];
    __shared__ float red[8];
    __shared__ float scale_s;

    float ss = 0.f;
#pragma unroll
    for (int k = 0; k < 8; ++k) {
        int i = tid + k * 256;
        int h = i >> 6;
        float x  = g_xbc[(size_t)tok * CONVD + i];
        float yv = g_y0[(size_t)tok * DINNER + i] + g_y1[(size_t)tok * DINNER + i]
                 + Dv[h] * x;
        float z  = g_zx[(size_t)tok * DIN + i];
        float g  = yv * (z / (1.f + expf(-z)));
        gsh[i] = g;
        ss = fmaf(g, g, ss);
    }
#pragma unroll
    for (int o = 16; o; o >>= 1) ss += __shfl_xor_sync(0xffffffffu, ss, o);
    if ((tid & 31) == 0) red[tid >> 5] = ss;
    __syncthreads();
    if (tid == 0) {
        float tot = 0.f;
#pragma unroll
        for (int w = 0; w < 8; ++w) tot += red[w];
        scale_s = rsqrtf(tot / (float)DINNER + 1e-5f);
    }
    __syncthreads();
    float sc = scale_s;
#pragma unroll
    for (int k = 0; k < 8; ++k) {
        int i = tid + k * 256;
        g_hn[(size_t)tok * DINNER + i] = gsh[i] * sc * nw[i];
    }
}

// ================= Kernel 5: classifier GEMM =================
__global__ void __launch_bounds__(256) k_cls(const float* __restrict__ Wc,
                                             const float* __restrict__ bc,
                                             float* __restrict__ out)
{
    int tok0 = blockIdx.x * 16;
    int tid  = threadIdx.x;
    __shared__ float Ws[64 * 48];
    __shared__ float Hs[16 * 64];
    int tokl = tid >> 4;
    int c0   = (tid & 15) * 3;
    float a0 = 0.f, a1 = 0.f, a2 = 0.f;

    for (int k0 = 0; k0 < DINNER; k0 += 64) {
#pragma unroll
        for (int r = 0; r < 12; ++r) {
            int idx = tid + r * 256;
            Ws[idx] = Wc[(size_t)k0 * NCLS + idx];
        }
#pragma unroll
        for (int r = 0; r < 4; ++r) {
            int idx = tid + r * 256;
            Hs[idx] = g_hn[(size_t)(tok0 + (idx >> 6)) * DINNER + k0 + (idx & 63)];
        }
        __syncthreads();
#pragma unroll
        for (int kk = 0; kk < 64; ++kk) {
            float hv = Hs[tokl * 64 + kk];
            const float* wr = &Ws[kk * 48 + c0];
            a0 = fmaf(hv, wr[0], a0);
            a1 = fmaf(hv, wr[1], a1);
            a2 = fmaf(hv, wr[2], a2);
        }
        __syncthreads();
    }
    float* op = &out[(size_t)(tok0 + tokl) * NCLS + c0];
    op[0] = a0 + bc[c0];
    op[1] = a1 + bc[c0 + 1];
    op[2] = a2 + bc[c0 + 2];
}

// ================= launcher =================
extern "C" void kernel_launch(void* const* d_in, const int* in_sizes, int n_in,
                              void* d_out, int out_size)
{
    const float* inputs  = (const float*)d_in[0];
    const float* W_in    = (const float*)d_in[1];
    const float* conv_w  = (const float*)d_in[2];
    const float* conv_b  = (const float*)d_in[3];
    const float* dt_bias = (const float*)d_in[4];
    const float* A_log   = (const float*)d_in[5];
    const float* Dv      = (const float*)d_in[6];
    const float* norm_w  = (const float*)d_in[7];
    const float* W_cls   = (const float*)d_in[9];
    const float* b_cls   = (const float*)d_in[10];
    float* out = (float*)d_out;

    (void)in_sizes; (void)n_in; (void)out_size;

    // 1) bf16 split conversion + HMMA GEMM
    k_cvtA<<<(NTOK * DMODEL) / 256, 256>>>(inputs);
    {
        dim3 g(DMODEL / 32, NPAD / 32);
        k_cvtW<<<g, 256>>>(W_in);
    }
    {
        dim3 grid(NPAD / 128, NTOK / 128);   // 35 x 8
        k_gemm_mma<<<grid, 256>>>();
    }
    // 2) conv + activations + dt/dA
    {
        int tot = NTOK * (CONVD + NHEADS);
        k_conv<<<(tot + 255) / 256, 256>>>(conv_w, conv_b, dt_bias, A_log);
    }
    // 3) scan
    k_scan<<<128, 256>>>();
    // 4) gate + rmsnorm
    k_gatenorm<<<NTOK, 256>>>(Dv, norm_w);
    // 5) classifier
    k_cls<<<NTOK / 16, 256>>>(W_cls, b_cls, out);
}